// round 11
// baseline (speedup 1.0000x reference)
#include <cuda_runtime.h>
#include <cuda_bf16.h>

// B=512, T=1024, IN=1, H=64
#define TLEN 1024
#define HDIM 64
#define NTHR 256            // tid = 4*m + q : unit m (0..63), gate q (i,f,g,o)
#define NBLK 128            // 4 batches per block (2 fp32x2-packed pairs)

typedef unsigned long long u64;

__device__ __forceinline__ u64 fma2(u64 a, u64 b, u64 c) {
    u64 d;
    asm("fma.rn.f32x2 %0, %1, %2, %3;" : "=l"(d) : "l"(a), "l"(b), "l"(c));
    return d;
}
__device__ __forceinline__ u64 add2(u64 a, u64 b) {
    u64 d;
    asm("add.rn.f32x2 %0, %1, %2;" : "=l"(d) : "l"(a), "l"(b));
    return d;
}
__device__ __forceinline__ u64 mul2(u64 a, u64 b) {
    u64 d;
    asm("mul.rn.f32x2 %0, %1, %2;" : "=l"(d) : "l"(a), "l"(b));
    return d;
}
__device__ __forceinline__ u64 pack2(float lo, float hi) {
    u64 r;
    asm("mov.b64 %0, {%1, %2};" : "=l"(r) : "f"(lo), "f"(hi));
    return r;
}
__device__ __forceinline__ void unpack2(u64 v, float& lo, float& hi) {
    asm("mov.b64 {%0, %1}, %2;" : "=f"(lo), "=f"(hi) : "l"(v));
}
__device__ __forceinline__ float ex2f(float x) {
    float r; asm("ex2.approx.f32 %0, %1;" : "=f"(r) : "f"(x)); return r;
}
__device__ __forceinline__ float rcpf(float x) {
    float r; asm("rcp.approx.f32 %0, %1;" : "=f"(r) : "f"(x)); return r;
}
// Rows PRE-SCALED by -log2(e) (sigmoid) / -2*log2(e) (tanh):
//   sigmoid(a) = 1/(1+ex2(z));  tanh(a) = 2/(1+ex2(z)) - 1
#define NLOG2E  1.44269504f
#define N2LOG2E 2.88539008f

__global__ void __launch_bounds__(NTHR, 1) qlstm_kernel(
    const float* __restrict__ x,      // [512, 1024, 1]
    const float* __restrict__ W_ih,   // [256, 1]
    const float* __restrict__ W_hh,   // [256, 64]
    const float* __restrict__ b_ih,   // [256]
    const float* __restrict__ b_hh,   // [256]
    const float* __restrict__ W_lin,  // [1, 64]
    const float* __restrict__ b_lin,  // [1]
    float* __restrict__ out)          // [512]
{
    __shared__ __align__(16) float xs[4][TLEN];      // 16 KB
    __shared__ __align__(16) u64 hsm[2][2][HDIM];    // 2 KB: [buf][pair][k] packed (b_lo,b_hi)

    const int tid = threadIdx.x;
    const int q   = tid & 3;      // gate: 0=i 1=f 2=g(tanh) 3=o
    const int m   = tid >> 2;     // hidden unit 0..63
    const int bb  = blockIdx.x * 4;

    // ---- stage x (coalesced, one-time) ----
    for (int i = tid; i < 4 * TLEN; i += NTHR)
        xs[i >> 10][i & (TLEN - 1)] = x[(bb + (i >> 10)) * TLEN + (i & (TLEN - 1))];

    // ---- one full-K W_hh row -> 64 broadcast-packed u64 regs, prescaled ----
    const int   row = q * 64 + m;
    const float scl = (q == 2) ? -N2LOG2E : -NLOG2E;
    u64 w2[64];
    {
        const float4* wr = reinterpret_cast<const float4*>(W_hh + row * HDIM);
        #pragma unroll
        for (int k = 0; k < 16; k++) {
            float4 v = wr[k];
            w2[4 * k + 0] = pack2(scl * v.x, scl * v.x);
            w2[4 * k + 1] = pack2(scl * v.y, scl * v.y);
            w2[4 * k + 2] = pack2(scl * v.z, scl * v.z);
            w2[4 * k + 3] = pack2(scl * v.w, scl * v.w);
        }
    }
    const float wih = scl * W_ih[row];
    const float bia = scl * (b_ih[row] + b_hh[row]);

    for (int i = tid; i < 2 * 2 * HDIM; i += NTHR)
        reinterpret_cast<u64*>(hsm)[i] = 0ull;

    u64 c2[2] = {0ull, 0ull};   // cell state, valid in q==0 lanes only
    __syncthreads();

    const unsigned FULL = 0xffffffffu;
    const u64 TWO2  = pack2(2.0f, 2.0f);
    const u64 NONE2 = pack2(-1.0f, -1.0f);
    const u64 NL2   = pack2(-N2LOG2E, -N2LOG2E);

    auto step = [&](int t, const u64 (*hin)[HDIM], u64 (*hout)[HDIM]) {
        #pragma unroll
        for (int pr = 0; pr < 2; pr++) {
            const float x0 = xs[2 * pr][t];
            const float x1 = xs[2 * pr + 1][t];
            // 4 split accumulators (depth 16 each); bias+x in chain 0
            u64 a0 = pack2(fmaf(x0, wih, bia), fmaf(x1, wih, bia));
            u64 a1 = 0ull, a2 = 0ull, a3 = 0ull;
            const ulonglong2* hp = reinterpret_cast<const ulonglong2*>(hin[pr]);
            #pragma unroll
            for (int kc = 0; kc < 8; kc++) {
                ulonglong2 va = hp[4 * kc + 0];
                ulonglong2 vb = hp[4 * kc + 1];
                ulonglong2 vc = hp[4 * kc + 2];
                ulonglong2 vd = hp[4 * kc + 3];
                a0 = fma2(w2[8 * kc + 0], va.x, a0);
                a1 = fma2(w2[8 * kc + 1], va.y, a1);
                a2 = fma2(w2[8 * kc + 2], vb.x, a2);
                a3 = fma2(w2[8 * kc + 3], vb.y, a3);
                a0 = fma2(w2[8 * kc + 4], vc.x, a0);
                a1 = fma2(w2[8 * kc + 5], vc.y, a1);
                a2 = fma2(w2[8 * kc + 6], vd.x, a2);
                a3 = fma2(w2[8 * kc + 7], vd.y, a3);
            }
            const u64 z2 = add2(add2(a0, a2), add2(a1, a3));  // (z_b0, z_b1)

            // own-gate activation, packed across the 2 batches
            float zl, zh; unpack2(z2, zl, zh);
            const u64 r2  = pack2(rcpf(1.0f + ex2f(zl)), rcpf(1.0f + ex2f(zh)));
            const u64 th2 = fma2(TWO2, r2, NONE2);
            const u64 act2 = (q == 2) ? th2 : r2;   // tanh lane vs sigmoid lanes

            // gather f,g,o to the q==0 lane (width-4 shuffles)
            const u64 f2 = __shfl_down_sync(FULL, act2, 1, 4);
            const u64 g2 = __shfl_down_sync(FULL, act2, 2, 4);
            const u64 o2 = __shfl_down_sync(FULL, act2, 3, 4);

            // packed cell update (q!=0 lanes compute garbage, never read)
            c2[pr] = fma2(f2, c2[pr], mul2(act2, g2));
            const u64 tz = mul2(c2[pr], NL2);
            float tl, th; unpack2(tz, tl, th);
            const u64 tr2 = pack2(rcpf(1.0f + ex2f(tl)), rcpf(1.0f + ex2f(th)));
            const u64 tc2 = fma2(TWO2, tr2, NONE2);
            if (q == 0) hout[pr][m] = mul2(o2, tc2);   // h for both batches
        }
    };

    #pragma unroll 1
    for (int t = 0; t < TLEN; t += 2) {
        step(t,     hsm[0], hsm[1]);
        __syncthreads();
        step(t + 1, hsm[1], hsm[0]);
        __syncthreads();
    }
    // t=1023 (odd) wrote hsm[0] -> final h in hsm[0]

    // ---- epilogue: out[b] = h_final . W_lin + b_lin ----
    const int w = tid >> 5, lane = tid & 31;
    if (w < 4) {
        const int pr = w >> 1, half = w & 1;
        float l0, h0, l1, h1;
        unpack2(hsm[0][pr][lane],      l0, h0);
        unpack2(hsm[0][pr][lane + 32], l1, h1);
        const float e0 = half ? h0 : l0;
        const float e1 = half ? h1 : l1;
        float v = fmaf(e0, W_lin[lane], e1 * W_lin[lane + 32]);
        #pragma unroll
        for (int d = 16; d >= 1; d >>= 1)
            v += __shfl_xor_sync(FULL, v, d);
        if (lane == 0) out[bb + 2 * pr + half] = v + b_lin[0];
    }
}

extern "C" void kernel_launch(void* const* d_in, const int* in_sizes, int n_in,
                              void* d_out, int out_size) {
    const float* x     = (const float*)d_in[0];
    const float* W_ih  = (const float*)d_in[1];
    const float* W_hh  = (const float*)d_in[2];
    const float* b_ih  = (const float*)d_in[3];
    const float* b_hh  = (const float*)d_in[4];
    const float* W_lin = (const float*)d_in[5];
    const float* b_lin = (const float*)d_in[6];
    float* out = (float*)d_out;

    qlstm_kernel<<<NBLK, NTHR>>>(x, W_ih, W_hh, b_ih, b_hh, W_lin, b_lin, out);
}

// round 12
// speedup vs baseline: 1.6095x; 1.6095x over previous
#include <cuda_runtime.h>
#include <cuda_bf16.h>

// B=512, T=1024, IN=1, H=64
#define TLEN 1024
#define HDIM 64
#define GB   2              // batches per block (weights shared across both)
#define NTHR 128            // 64 units x 2 gate-pairs
#define NBLK 256            // 512 / GB -> 2 co-resident blocks per SM

typedef unsigned long long u64;

__device__ __forceinline__ u64 fma2(u64 a, u64 b, u64 c) {
    u64 d;
    asm("fma.rn.f32x2 %0, %1, %2, %3;" : "=l"(d) : "l"(a), "l"(b), "l"(c));
    return d;
}
__device__ __forceinline__ u64 add2(u64 a, u64 b) {
    u64 d;
    asm("add.rn.f32x2 %0, %1, %2;" : "=l"(d) : "l"(a), "l"(b));
    return d;
}
__device__ __forceinline__ u64 pack2(float lo, float hi) {
    u64 r;
    asm("mov.b64 %0, {%1, %2};" : "=l"(r) : "f"(lo), "f"(hi));
    return r;
}
__device__ __forceinline__ float lo_add_hi(u64 v) {
    float lo, hi;
    asm("mov.b64 {%0, %1}, %2;" : "=f"(lo), "=f"(hi) : "l"(v));
    return lo + hi;
}
__device__ __forceinline__ float ex2f(float x) {
    float r; asm("ex2.approx.f32 %0, %1;" : "=f"(r) : "f"(x)); return r;
}
__device__ __forceinline__ float rcpf(float x) {
    float r; asm("rcp.approx.f32 %0, %1;" : "=f"(r) : "f"(x)); return r;
}
// Gate rows PRE-SCALED by -log2(e) (sigmoid rows) or -2*log2(e) (tanh row):
//   sigmoid(a) = 1/(1+ex2(z));   tanh(a) = 2/(1+ex2(z)) - 1
#define NLOG2E  1.44269504f
#define N2LOG2E 2.88539008f

__global__ void __launch_bounds__(NTHR, 2) qlstm_kernel(
    const float* __restrict__ x,      // [512, 1024, 1]
    const float* __restrict__ W_ih,   // [256, 1]
    const float* __restrict__ W_hh,   // [256, 64]
    const float* __restrict__ b_ih,   // [256]
    const float* __restrict__ b_hh,   // [256]
    const float* __restrict__ W_lin,  // [1, 64]
    const float* __restrict__ b_lin,  // [1]
    float* __restrict__ out)          // [512]
{
    __shared__ __align__(16) float xs[GB][TLEN];       // 8 KB
    __shared__ __align__(16) float hsm[2][GB][HDIM];   // 1 KB, double-buffered

    const int tid = threadIdx.x;
    const int p   = tid & 1;      // 0 -> gates {i,f}; 1 -> gates {g,o}
    const int m   = tid >> 1;     // hidden unit 0..63
    const int bb  = blockIdx.x * GB;

    // ---- stage x (coalesced, one-time) ----
    for (int i = tid; i < GB * TLEN; i += NTHR)
        xs[i >> 10][i & (TLEN - 1)] = x[(bb + (i >> 10)) * TLEN + (i & (TLEN - 1))];

    // ---- 2 full-K W_hh rows -> regs, prescaled (128 regs) ----
    const int   r0   = p ? 128 + m : m;        // g-row  : i-row
    const int   r1   = p ? 192 + m : 64 + m;   // o-row  : f-row
    const float scl0 = p ? -N2LOG2E : -NLOG2E; // tanh row gets 2x scale
    const float scl1 = -NLOG2E;

    u64 w0[32], w1[32];
    {
        const float4* a = reinterpret_cast<const float4*>(W_hh + r0 * HDIM);
        const float4* b = reinterpret_cast<const float4*>(W_hh + r1 * HDIM);
        #pragma unroll
        for (int k = 0; k < 16; k++) {
            float4 v = a[k];
            w0[2 * k]     = pack2(scl0 * v.x, scl0 * v.y);
            w0[2 * k + 1] = pack2(scl0 * v.z, scl0 * v.w);
            float4 u = b[k];
            w1[2 * k]     = pack2(scl1 * u.x, scl1 * u.y);
            w1[2 * k + 1] = pack2(scl1 * u.z, scl1 * u.w);
        }
    }
    const float wih0 = scl0 * W_ih[r0], bia0 = scl0 * (b_ih[r0] + b_hh[r0]);
    const float wih1 = scl1 * W_ih[r1], bia1 = scl1 * (b_ih[r1] + b_hh[r1]);

    for (int i = tid; i < 2 * GB * HDIM; i += NTHR)
        reinterpret_cast<float*>(hsm)[i] = 0.0f;

    float c[GB] = {0.0f, 0.0f};   // live in p==0 lanes (p==1 copy is dead)
    __syncthreads();

    const unsigned FULL = 0xffffffffu;

    auto step = [&](int t, const float (*hin)[HDIM], float (*hout)[HDIM]) {
        // --- both batches interleaved; h loaded in 4 chunks of 8 u64 each ---
        u64 aA0[GB], aB0[GB], aA1[GB], aB1[GB];
        #pragma unroll
        for (int g = 0; g < GB; g++) {
            const float xv = xs[g][t];
            aA0[g] = pack2(fmaf(xv, wih0, bia0), 0.0f);
            aB0[g] = 0ull;
            aA1[g] = pack2(fmaf(xv, wih1, bia1), 0.0f);
            aB1[g] = 0ull;
        }
        #pragma unroll
        for (int ch = 0; ch < 4; ch++) {
            u64 hc[GB][8];
            #pragma unroll
            for (int g = 0; g < GB; g++) {
                const ulonglong2* hp =
                    reinterpret_cast<const ulonglong2*>(hin[g]) + 4 * ch;
                #pragma unroll
                for (int k = 0; k < 4; k++) {
                    ulonglong2 v = hp[k];
                    hc[g][2 * k] = v.x; hc[g][2 * k + 1] = v.y;
                }
            }
            #pragma unroll
            for (int k = 0; k < 4; k++) {
                #pragma unroll
                for (int g = 0; g < GB; g++) {
                    aA0[g] = fma2(w0[8 * ch + k],     hc[g][k],     aA0[g]);
                    aB0[g] = fma2(w0[8 * ch + 4 + k], hc[g][4 + k], aB0[g]);
                    aA1[g] = fma2(w1[8 * ch + k],     hc[g][k],     aA1[g]);
                    aB1[g] = fma2(w1[8 * ch + 4 + k], hc[g][4 + k], aB1[g]);
                }
            }
        }
        // --- tails, both batches interleaved ---
        float z0[GB], z1[GB], a0[GB], a1[GB], tg[GB];
        #pragma unroll
        for (int g = 0; g < GB; g++) {
            z0[g] = lo_add_hi(add2(aA0[g], aB0[g]));
            z1[g] = lo_add_hi(add2(aA1[g], aB1[g]));
        }
        #pragma unroll
        for (int g = 0; g < GB; g++) {
            a0[g] = rcpf(1.0f + ex2f(z0[g]));   // p0: sig(i)  p1: (tanh(g)+1)/2
            a1[g] = rcpf(1.0f + ex2f(z1[g]));   // p0: sig(f)  p1: sig(o)
            tg[g] = fmaf(2.0f, a0[g], -1.0f);   // p1: tanh(g)
        }
        // two INDEPENDENT shuffles: p0 receives tanh(g) and sig(o) together
        float gr[GB], ox[GB];
        #pragma unroll
        for (int g = 0; g < GB; g++) {
            gr[g] = __shfl_xor_sync(FULL, p ? tg[g] : a0[g], 1);
            ox[g] = __shfl_xor_sync(FULL, a1[g], 1);
        }
        #pragma unroll
        for (int g = 0; g < GB; g++) {
            // p0: c = sig(f)*c + sig(i)*tanh(g)   (p1 lanes: garbage, never read)
            c[g] = fmaf(a1[g], c[g], a0[g] * gr[g]);
            const float tc = fmaf(2.0f, rcpf(1.0f + ex2f(-N2LOG2E * c[g])), -1.0f);
            if (p == 0) hout[g][m] = ox[g] * tc;   // h = sig(o)*tanh(c)
        }
    };

    #pragma unroll 1
    for (int t = 0; t < TLEN; t += 2) {
        step(t,     hsm[0], hsm[1]);
        __syncthreads();
        step(t + 1, hsm[1], hsm[0]);
        __syncthreads();
    }
    // t=1023 (odd) wrote hsm[0] -> final h in hsm[0]

    // ---- epilogue: out[b] = h_final . W_lin + b_lin ----
    const int w = tid >> 5, lane = tid & 31;
    if (w < GB) {
        const float* hf = hsm[0][w];
        float v = fmaf(hf[lane], W_lin[lane], hf[lane + 32] * W_lin[lane + 32]);
        #pragma unroll
        for (int d = 16; d >= 1; d >>= 1)
            v += __shfl_xor_sync(FULL, v, d);
        if (lane == 0) out[bb + w] = v + b_lin[0];
    }
}

extern "C" void kernel_launch(void* const* d_in, const int* in_sizes, int n_in,
                              void* d_out, int out_size) {
    const float* x     = (const float*)d_in[0];
    const float* W_ih  = (const float*)d_in[1];
    const float* W_hh  = (const float*)d_in[2];
    const float* b_ih  = (const float*)d_in[3];
    const float* b_hh  = (const float*)d_in[4];
    const float* W_lin = (const float*)d_in[5];
    const float* b_lin = (const float*)d_in[6];
    float* out = (float*)d_out;

    qlstm_kernel<<<NBLK, NTHR>>>(x, W_ih, W_hh, b_ih, b_hh, W_lin, b_lin, out);
}